// round 14
// baseline (speedup 1.0000x reference)
#include <cuda_runtime.h>
#include <cuda_fp16.h>
#include <math.h>
#include <stdint.h>

// Problem constants
#define BB 4
#define SS 2048
#define DD 1024
#define HH 16
#define DHH 64
#define FFD 4096
#define NROWS (BB*SS)          // 8192

// ---------------- scratch (device globals: allocation-guard safe) ----------
__device__ __half g_h   [(size_t)NROWS * DD];     // LN1 out
__device__ __half g_h2  [(size_t)NROWS * DD];     // LN2 out
__device__ __half g_wqkv[(size_t)3 * DD * DD];    // [3072 (N), 1024 (K)], q-part pre-scaled 0.125
__device__ __half g_wot [(size_t)DD * DD];        // wo^T
__device__ __half g_w1t [(size_t)FFD * DD];       // w1^T
__device__ __half g_w2t [(size_t)DD * FFD];       // w2^T
__device__ __half g_qkv [(size_t)NROWS * 3 * DD]; // [8192, 3072]
__device__ __half g_attn[(size_t)NROWS * DD];     // attention out
__device__ __half g_ff1 [(size_t)NROWS * FFD];    // FFN hidden

// ---------------- helpers ---------------------------------------------------
__device__ __forceinline__ uint32_t smem_u32(const void* p) {
    return (uint32_t)__cvta_generic_to_shared(p);
}

__device__ __forceinline__ uint32_t pack_h2(float lo, float hi) {
    __half2 p = __floats2half2_rn(lo, hi);
    return *reinterpret_cast<uint32_t*>(&p);
}

__device__ __forceinline__ void cp16(uint32_t dst, const void* src) {
    asm volatile("cp.async.cg.shared.global [%0], [%1], 16;" :: "r"(dst), "l"(src));
}
#define CP_COMMIT() asm volatile("cp.async.commit_group;" ::: "memory")
#define CP_WAIT1()  asm volatile("cp.async.wait_group 1;" ::: "memory")
#define CP_WAIT0()  asm volatile("cp.async.wait_group 0;" ::: "memory")

__device__ __forceinline__ void mma_f16(float* c, const uint32_t* a, const uint32_t* b) {
    asm volatile(
        "mma.sync.aligned.m16n8k16.row.col.f32.f16.f16.f32 "
        "{%0,%1,%2,%3}, {%4,%5,%6,%7}, {%8,%9}, {%0,%1,%2,%3};"
        : "+f"(c[0]), "+f"(c[1]), "+f"(c[2]), "+f"(c[3])
        : "r"(a[0]), "r"(a[1]), "r"(a[2]), "r"(a[3]), "r"(b[0]), "r"(b[1]));
}

__device__ __forceinline__ void ldsm_x4(uint32_t* r, uint32_t addr) {
    asm volatile("ldmatrix.sync.aligned.m8n8.x4.shared.b16 {%0,%1,%2,%3}, [%4];"
        : "=r"(r[0]), "=r"(r[1]), "=r"(r[2]), "=r"(r[3]) : "r"(addr));
}
__device__ __forceinline__ void ldsm_x2(uint32_t* r, uint32_t addr) {
    asm volatile("ldmatrix.sync.aligned.m8n8.x2.shared.b16 {%0,%1}, [%2];"
        : "=r"(r[0]), "=r"(r[1]) : "r"(addr));
}
__device__ __forceinline__ void ldsm_x2_trans(uint32_t* r, uint32_t addr) {
    asm volatile("ldmatrix.sync.aligned.m8n8.x2.trans.shared.b16 {%0,%1}, [%2];"
        : "=r"(r[0]), "=r"(r[1]) : "r"(addr));
}

__device__ __forceinline__ float gelu_exact(float v) {
    return 0.5f * v * (1.0f + erff(v * 0.70710678118654752f));
}

// ---------------- LayerNorm: warp-per-row, 8 rows per 256-thr block -------
__global__ __launch_bounds__(256) void ln_kernel(const float* __restrict__ x,
                                                 const float* __restrict__ gamma,
                                                 const float* __restrict__ beta,
                                                 __half* __restrict__ out) {
    int warp = threadIdx.x >> 5, lane = threadIdx.x & 31;
    int row = blockIdx.x * 8 + warp;
    const float* xr = x + (size_t)row * DD;

    float4 v[8];
    float s = 0.f;
#pragma unroll
    for (int k = 0; k < 8; ++k) {
        v[k] = *(const float4*)(xr + k * 128 + lane * 4);
        s += v[k].x + v[k].y + v[k].z + v[k].w;
    }
#pragma unroll
    for (int off = 16; off; off >>= 1) s += __shfl_xor_sync(0xffffffffu, s, off);
    float mean = s * (1.0f / DD);

    float sq = 0.f;
#pragma unroll
    for (int k = 0; k < 8; ++k) {
        float dx = v[k].x - mean, dy = v[k].y - mean;
        float dz = v[k].z - mean, dw = v[k].w - mean;
        sq += dx * dx + dy * dy + dz * dz + dw * dw;
    }
#pragma unroll
    for (int off = 16; off; off >>= 1) sq += __shfl_xor_sync(0xffffffffu, sq, off);
    float rstd = rsqrtf(sq * (1.0f / DD) + 1e-5f);

#pragma unroll
    for (int k = 0; k < 8; ++k) {
        float4 g4 = *(const float4*)(gamma + k * 128 + lane * 4);
        float4 b4 = *(const float4*)(beta + k * 128 + lane * 4);
        uint2 o;
        o.x = pack_h2((v[k].x - mean) * rstd * g4.x + b4.x,
                      (v[k].y - mean) * rstd * g4.y + b4.y);
        o.y = pack_h2((v[k].z - mean) * rstd * g4.z + b4.z,
                      (v[k].w - mean) * rstd * g4.w + b4.w);
        *(uint2*)(out + (size_t)row * DD + k * 128 + lane * 4) = o;
    }
}

// ---------------- pack wq/wk/wv [H,D,DH] -> [3072 (N), 1024 (K)] fp16 -----
__global__ __launch_bounds__(256) void repack_wqkv(const float* __restrict__ wq,
                                                   const float* __restrict__ wk,
                                                   const float* __restrict__ wv,
                                                   __half* __restrict__ wt) {
    __shared__ float t[32][33];
    int part = blockIdx.z >> 4, h = blockIdx.z & 15;
    int db = blockIdx.y * 32;
    int eb = blockIdx.x * 32;
    const float* w = (part == 0) ? wq : (part == 1) ? wk : wv;
    const float* wb = w + ((size_t)h * DD + db) * DHH + eb;
#pragma unroll
    for (int i = 0; i < 32; i += 8)
        t[threadIdx.y + i][threadIdx.x] = wb[(size_t)(threadIdx.y + i) * DHH + threadIdx.x];
    __syncthreads();
    float scale = (part == 0) ? 0.125f : 1.0f;
    int nbase = part * DD + h * DHH + eb;
#pragma unroll
    for (int i = 0; i < 32; i += 8)
        wt[(size_t)(nbase + threadIdx.y + i) * DD + db + threadIdx.x] =
            __float2half_rn(t[threadIdx.x][threadIdx.y + i] * scale);
}

// ---------------- transpose [R,C] fp32 -> [C,R] fp16 ----------------------
__global__ __launch_bounds__(256) void transpose_kernel(const float* __restrict__ in,
                                                        __half* __restrict__ out,
                                                        int R, int C) {
    __shared__ float t[32][33];
    int rb = blockIdx.y * 32, cb = blockIdx.x * 32;
#pragma unroll
    for (int i = 0; i < 32; i += 8)
        t[threadIdx.y + i][threadIdx.x] = in[(size_t)(rb + threadIdx.y + i) * C + cb + threadIdx.x];
    __syncthreads();
#pragma unroll
    for (int i = 0; i < 32; i += 8)
        out[(size_t)(cb + threadIdx.y + i) * R + rb + threadIdx.x] =
            __float2half_rn(t[threadIdx.x][threadIdx.y + i]);
}

// ---------------- fp16 mma.sync GEMM: C[M,N] = A[M,K] @ Wt[N,K]^T ---------
// CTA tile 128x256, 8 warps (2m x 4n), warp tile 64x64 (4x8 m16n8k16).
// Fragment feed via ldmatrix (A: x4 per mt; B: x4 per nt-pair).
// Smem/stage: A 128 rows + B 256 rows, 144B row stride (conflict-free LDSM).
#define GROW_B 144
#define STAGE_U (384 * 36)                        // 13824 u32 = 55296 B
#define NSTG 3
#define GEMM_SMEM (NSTG * STAGE_U * 4)            // 165888 bytes

template<int EPI>
__global__ __launch_bounds__(256)
void gemm_f16_kernel(const __half* __restrict__ A,
                     const __half* __restrict__ Wt,
                     void* __restrict__ Cv,
                     const float* __restrict__ bias, const float* __restrict__ res,
                     int M, int N, int K) {
    extern __shared__ uint32_t smem[];
    uint32_t sbase = smem_u32(smem);
    int tid = threadIdx.x;
    int wid = tid >> 5, lane = tid & 31;
    int g = lane >> 2, t = lane & 3;
    int l8 = lane & 7, mi = lane >> 3;
    int warp_m = wid >> 2, warp_n = wid & 3;       // 2 x 4
    int m0 = blockIdx.y << 7, n0 = blockIdx.x << 8;

    const __half* Ab = A + (size_t)m0 * K;
    const __half* Bb = Wt + (size_t)n0 * K;
    int kt = K >> 6;

    float acc[4][8][4] = {};

    uint32_t lm_off = (uint32_t)((((mi & 1) << 3) + l8) * GROW_B + ((mi >> 1) << 4));

    // stage rows: 0..127 = A, 128..383 = B (256 N-rows)
    auto load_stage = [&](int s, int jt) {
        uint32_t sS = sbase + s * STAGE_U * 4;
        int k0 = jt << 6;
#pragma unroll
        for (int i = 0; i < 12; ++i) {
            int f = i * 256 + tid;                 // 0..3071
            int row = f >> 3, ch = f & 7;
            const __half* src = (row < 128)
                ? Ab + (size_t)row * K + k0 + ch * 8
                : Bb + (size_t)(row - 128) * K + k0 + ch * 8;
            cp16(sS + (uint32_t)(row * GROW_B + ch * 16), src);
        }
    };

#pragma unroll
    for (int s = 0; s < NSTG - 1; ++s) { load_stage(s, s); CP_COMMIT(); }

    for (int j = 0; j < kt; ++j) {
        CP_WAIT1();
        __syncthreads();
        uint32_t sAu = sbase + (j % NSTG) * STAGE_U * 4;
        uint32_t sBu = sAu + (uint32_t)(128 * GROW_B);
#pragma unroll
        for (int ks = 0; ks < 4; ++ks) {
            uint32_t kboff = (uint32_t)(ks * 32);
            uint32_t a[4][4], b[8][2];
#pragma unroll
            for (int mt = 0; mt < 4; ++mt)
                ldsm_x4(a[mt], sAu + (uint32_t)((warp_m * 64 + mt * 16) * GROW_B)
                               + kboff + lm_off);
#pragma unroll
            for (int ntp = 0; ntp < 4; ++ntp) {
                uint32_t r[4];
                ldsm_x4(r, sBu + (uint32_t)((warp_n * 64 + ntp * 16) * GROW_B)
                           + kboff + lm_off);
                b[2 * ntp][0]     = r[0]; b[2 * ntp][1]     = r[2];
                b[2 * ntp + 1][0] = r[1]; b[2 * ntp + 1][1] = r[3];
            }
#pragma unroll
            for (int mt = 0; mt < 4; ++mt)
#pragma unroll
                for (int nt = 0; nt < 8; ++nt)
                    mma_f16(acc[mt][nt], a[mt], b[nt]);
        }
        if (j + NSTG - 1 < kt) load_stage((j + NSTG - 1) % NSTG, j + NSTG - 1);
        CP_COMMIT();
    }

#pragma unroll
    for (int mt = 0; mt < 4; ++mt) {
#pragma unroll
        for (int nt = 0; nt < 8; ++nt) {
#pragma unroll
            for (int half = 0; half < 2; ++half) {
                int row = m0 + warp_m * 64 + mt * 16 + g + half * 8;
                int col = n0 + warp_n * 64 + nt * 8 + 2 * t;
                float v0 = acc[mt][nt][half * 2 + 0];
                float v1 = acc[mt][nt][half * 2 + 1];
                size_t ga = (size_t)row * N + col;
                if (EPI == 0) {
                    *(uint32_t*)((__half*)Cv + ga) = pack_h2(v0, v1);
                } else if (EPI == 2) {
                    v0 = gelu_exact(v0 + bias[col]);
                    v1 = gelu_exact(v1 + bias[col + 1]);
                    *(uint32_t*)((__half*)Cv + ga) = pack_h2(v0, v1);
                } else {
                    float2 r = *(const float2*)(res + ga);
                    if (EPI == 3) { v0 += bias[col]; v1 += bias[col + 1]; }
                    float2 o; o.x = v0 + r.x; o.y = v1 + r.y;
                    *(float2*)((float*)Cv + ga) = o;
                }
            }
        }
    }
}

// ---------------- Flash attention (causal), fp16 mma + ldmatrix + cp.async --
#define FA_Q_U    4608                       // 128*36
#define FA_KV_U   2304                       // 64*36
#define FA_STG_U  (2 * FA_KV_U)              // 4608 (K then V)
#define FA_SMEM   ((FA_Q_U + 2 * FA_STG_U) * 4)   // 55296 bytes

__global__ __launch_bounds__(256) void flash_attn_mma_kernel(const __half* __restrict__ qkv,
                                                             __half* __restrict__ attn) {
    extern __shared__ uint32_t sm[];
    uint32_t sbase = smem_u32(sm);
    int tid = threadIdx.x;
    int wid = tid >> 5, lane = tid & 31;
    int g = lane >> 2, t = lane & 3;
    int l8 = lane & 7, l16 = lane & 15;
    int mi = lane >> 3;
    int qt = (int)gridDim.x - 1 - (int)blockIdx.x;
    int b = blockIdx.y >> 4, h = blockIdx.y & 15;
    int q0 = qt * 128;
    const __half* qbase = qkv + ((size_t)(b * SS + q0)) * (3 * DD) + h * DHH;
    const __half* kbase = qkv + ((size_t)(b * SS)) * (3 * DD) + DD + h * DHH;
    const __half* vbase = qkv + ((size_t)(b * SS)) * (3 * DD) + 2 * DD + h * DHH;

#pragma unroll
    for (int it = 0; it < 4; ++it) {
        int f = it * 256 + tid, r = f >> 3, ch = f & 7;
        uint4 v = *(const uint4*)(qbase + (size_t)r * (3 * DD) + ch * 8);
        *(uint4*)((char*)sm + r * 144 + ch * 16) = v;
    }

    int mrow = wid * 16;
    int ntiles = 2 * qt + 2;

    auto load_kv = [&](int s, int kt2) {
        uint32_t kvb = sbase + (FA_Q_U + s * FA_STG_U) * 4;
#pragma unroll
        for (int it = 0; it < 4; ++it) {
            int f = it * 256 + tid;
            int r = f >> 3, ch = f & 7;
            int key = kt2 * 64 + (r & 63);
            const __half* src = ((r < 64) ? kbase : vbase) + (size_t)key * (3 * DD) + ch * 8;
            uint32_t dst = kvb + ((r < 64) ? 0u : (uint32_t)(FA_KV_U * 4))
                         + (uint32_t)((r & 63) * 144 + ch * 16);
            cp16(dst, src);
        }
    };

    float acc_o[8][4] = {};
    float m0r = -INFINITY, m1r = -INFINITY, l0r = 0.f, l1r = 0.f;

    load_kv(0, 0);
    CP_COMMIT();

    for (int kt = 0; kt < ntiles; ++kt) {
        int cur = kt & 1;
        uint32_t ksb = sbase + (FA_Q_U + cur * FA_STG_U) * 4;
        uint32_t vsb = ksb + FA_KV_U * 4;
        CP_WAIT0();
        __syncthreads();
        if (kt + 1 < ntiles) load_kv((kt + 1) & 1, kt + 1);
        CP_COMMIT();

        float acc_s[8][4] = {};
#pragma unroll
        for (int ks = 0; ks < 4; ++ks) {
            uint32_t aq[4];
            uint32_t qaddr = sbase + (uint32_t)((mrow + ((mi & 1) << 3) + l8) * 144
                                                + ks * 32 + ((mi >> 1) << 4));
            ldsm_x4(aq, qaddr);
#pragma unroll
            for (int nt = 0; nt < 8; ++nt) {
                uint32_t bk[2];
                uint32_t kaddr = ksb + (uint32_t)((nt * 8 + l8) * 144
                                                  + ks * 32 + (((lane >> 3) & 1) << 4));
                ldsm_x2(bk, kaddr);
                mma_f16(acc_s[nt], aq, bk);
            }
        }

        if (kt >= 2 * qt) {
            int r0 = q0 + mrow + g, r1 = r0 + 8;
#pragma unroll
            for (int nt = 0; nt < 8; ++nt) {
                int c0 = kt * 64 + nt * 8 + 2 * t;
                if (c0     > r0) acc_s[nt][0] = -INFINITY;
                if (c0 + 1 > r0) acc_s[nt][1] = -INFINITY;
                if (c0     > r1) acc_s[nt][2] = -INFINITY;
                if (c0 + 1 > r1) acc_s[nt][3] = -INFINITY;
            }
        }

        float mx0 = -INFINITY, mx1 = -INFINITY;
#pragma unroll
        for (int nt = 0; nt < 8; ++nt) {
            mx0 = fmaxf(mx0, fmaxf(acc_s[nt][0], acc_s[nt][1]));
            mx1 = fmaxf(mx1, fmaxf(acc_s[nt][2], acc_s[nt][3]));
        }
        mx0 = fmaxf(mx0, __shfl_xor_sync(0xffffffffu, mx0, 1));
        mx0 = fmaxf(mx0, __shfl_xor_sync(0xffffffffu, mx0, 2));
        mx1 = fmaxf(mx1, __shfl_xor_sync(0xffffffffu, mx1, 1));
        mx1 = fmaxf(mx1, __shfl_xor_sync(0xffffffffu, mx1, 2));
        float mn0 = fmaxf(m0r, mx0), mn1 = fmaxf(m1r, mx1);
        float al0 = __expf(m0r - mn0), al1 = __expf(m1r - mn1);
        float rs0 = 0.f, rs1 = 0.f;
#pragma unroll
        for (int nt = 0; nt < 8; ++nt) {
            acc_s[nt][0] = __expf(acc_s[nt][0] - mn0);
            acc_s[nt][1] = __expf(acc_s[nt][1] - mn0);
            acc_s[nt][2] = __expf(acc_s[nt][2] - mn1);
            acc_s[nt][3] = __expf(acc_s[nt][3] - mn1);
            rs0 += acc_s[nt][0] + acc_s[nt][1];
            rs1 += acc_s[nt][2] + acc_s[nt][3];
        }
        rs0 += __shfl_xor_sync(0xffffffffu, rs0, 1);
        rs0 += __shfl_xor_sync(0xffffffffu, rs0, 2);
        rs1 += __shfl_xor_sync(0xffffffffu, rs1, 1);
        rs1 += __shfl_xor_sync(0xffffffffu, rs1, 2);
        l0r = l0r * al0 + rs0;  m0r = mn0;
        l1r = l1r * al1 + rs1;  m1r = mn1;
#pragma unroll
        for (int nt = 0; nt < 8; ++nt) {
            acc_o[nt][0] *= al0; acc_o[nt][1] *= al0;
            acc_o[nt][2] *= al1; acc_o[nt][3] *= al1;
        }

#pragma unroll
        for (int ks = 0; ks < 4; ++ks) {
            uint32_t ap[4];
            ap[0] = pack_h2(acc_s[2 * ks][0],     acc_s[2 * ks][1]);
            ap[1] = pack_h2(acc_s[2 * ks][2],     acc_s[2 * ks][3]);
            ap[2] = pack_h2(acc_s[2 * ks + 1][0], acc_s[2 * ks + 1][1]);
            ap[3] = pack_h2(acc_s[2 * ks + 1][2], acc_s[2 * ks + 1][3]);
            uint32_t vrow = vsb + (uint32_t)((ks * 16 + l16) * 144);
#pragma unroll
            for (int nt = 0; nt < 8; ++nt) {
                uint32_t bv[2];
                ldsm_x2_trans(bv, vrow + (uint32_t)(nt * 16));
                mma_f16(acc_o[nt], ap, bv);
            }
        }
    }

    float inv0 = 1.0f / l0r, inv1 = 1.0f / l1r;
    int r0 = q0 + mrow + g, r1 = r0 + 8;
#pragma unroll
    for (int nt = 0; nt < 8; ++nt) {
        int col = h * DHH + nt * 8 + 2 * t;
        *(uint32_t*)(attn + ((size_t)(b * SS + r0)) * DD + col) =
            pack_h2(acc_o[nt][0] * inv0, acc_o[nt][1] * inv0);
        *(uint32_t*)(attn + ((size_t)(b * SS + r1)) * DD + col) =
            pack_h2(acc_o[nt][2] * inv1, acc_o[nt][3] * inv1);
    }
}

// ---------------- launch ---------------------------------------------------
extern "C" void kernel_launch(void* const* d_in, const int* in_sizes, int n_in,
                              void* d_out, int out_size) {
    const float* x   = (const float*)d_in[0];
    const float* wq  = (const float*)d_in[2];
    const float* wk  = (const float*)d_in[3];
    const float* wv  = (const float*)d_in[4];
    const float* wo  = (const float*)d_in[5];
    const float* w1  = (const float*)d_in[6];
    const float* b1  = (const float*)d_in[7];
    const float* w2  = (const float*)d_in[8];
    const float* b2  = (const float*)d_in[9];
    const float* g1  = (const float*)d_in[10];
    const float* be1 = (const float*)d_in[11];
    const float* g2  = (const float*)d_in[12];
    const float* be2 = (const float*)d_in[13];
    float* out = (float*)d_out;

    __half *h, *h2, *wqkv, *wot, *w1t, *w2t, *qkv, *attn, *ff1;
    cudaGetSymbolAddress((void**)&h,    g_h);
    cudaGetSymbolAddress((void**)&h2,   g_h2);
    cudaGetSymbolAddress((void**)&wqkv, g_wqkv);
    cudaGetSymbolAddress((void**)&wot,  g_wot);
    cudaGetSymbolAddress((void**)&w1t,  g_w1t);
    cudaGetSymbolAddress((void**)&w2t,  g_w2t);
    cudaGetSymbolAddress((void**)&qkv,  g_qkv);
    cudaGetSymbolAddress((void**)&attn, g_attn);
    cudaGetSymbolAddress((void**)&ff1,  g_ff1);

    cudaFuncSetAttribute(gemm_f16_kernel<0>, cudaFuncAttributeMaxDynamicSharedMemorySize, GEMM_SMEM);
    cudaFuncSetAttribute(gemm_f16_kernel<1>, cudaFuncAttributeMaxDynamicSharedMemorySize, GEMM_SMEM);
    cudaFuncSetAttribute(gemm_f16_kernel<2>, cudaFuncAttributeMaxDynamicSharedMemorySize, GEMM_SMEM);
    cudaFuncSetAttribute(gemm_f16_kernel<3>, cudaFuncAttributeMaxDynamicSharedMemorySize, GEMM_SMEM);
    cudaFuncSetAttribute(flash_attn_mma_kernel, cudaFuncAttributeMaxDynamicSharedMemorySize, FA_SMEM);

    // weight repacks (per-launch, coalesced)
    repack_wqkv<<<dim3(2, 32, 48), dim3(32, 8)>>>(wq, wk, wv, wqkv);
    transpose_kernel<<<dim3(DD / 32, DD / 32),  dim3(32, 8)>>>(wo, wot, DD, DD);
    transpose_kernel<<<dim3(FFD / 32, DD / 32), dim3(32, 8)>>>(w1, w1t, DD, FFD);
    transpose_kernel<<<dim3(DD / 32, FFD / 32), dim3(32, 8)>>>(w2, w2t, FFD, DD);

    // 1. LN1 (fp16 out)
    ln_kernel<<<NROWS / 8, 256>>>(x, g1, be1, h);
    // 2. QKV projection: [8192,1024] @ [1024,3072] -> fp16
    gemm_f16_kernel<0><<<dim3(3 * DD / 256, NROWS / 128), 256, GEMM_SMEM>>>(
        h, wqkv, qkv, nullptr, nullptr, NROWS, 3 * DD, DD);
    // 3. flash attention
    flash_attn_mma_kernel<<<dim3(SS / 128, BB * HH), 256, FA_SMEM>>>(qkv, attn);
    // 4. out = x + attn @ wo   (fp32 out)
    gemm_f16_kernel<1><<<dim3(DD / 256, NROWS / 128), 256, GEMM_SMEM>>>(
        attn, wot, out, nullptr, x, NROWS, DD, DD);
    // 5. LN2 (fp16 out)
    ln_kernel<<<NROWS / 8, 256>>>(out, g2, be2, h2);
    // 6. ff1 = gelu(h2 @ w1 + b1)  -> fp16
    gemm_f16_kernel<2><<<dim3(FFD / 256, NROWS / 128), 256, GEMM_SMEM>>>(
        h2, w1t, ff1, b1, nullptr, NROWS, FFD, DD);
    // 7. out = out + ff1 @ w2 + b2   (fp32, in-place residual)
    gemm_f16_kernel<3><<<dim3(DD / 256, NROWS / 128), 256, GEMM_SMEM>>>(
        ff1, w2t, out, b2, out, NROWS, DD, FFD);
}

// round 16
// speedup vs baseline: 1.0772x; 1.0772x over previous
#include <cuda_runtime.h>
#include <cuda_fp16.h>
#include <math.h>
#include <stdint.h>

// Problem constants
#define BB 4
#define SS 2048
#define DD 1024
#define HH 16
#define DHH 64
#define FFD 4096
#define NROWS (BB*SS)          // 8192

// ---------------- scratch (device globals: allocation-guard safe) ----------
__device__ __half g_h   [(size_t)NROWS * DD];     // LN1 out
__device__ __half g_h2  [(size_t)NROWS * DD];     // LN2 out
__device__ __half g_wqkv[(size_t)3 * DD * DD];    // [3072 (N), 1024 (K)], q-part pre-scaled 0.125
__device__ __half g_wot [(size_t)DD * DD];        // wo^T
__device__ __half g_w1t [(size_t)FFD * DD];       // w1^T
__device__ __half g_w2t [(size_t)DD * FFD];       // w2^T
__device__ __half g_qkv [(size_t)NROWS * 3 * DD]; // [8192, 3072]
__device__ __half g_attn[(size_t)NROWS * DD];     // attention out
__device__ __half g_ff1 [(size_t)NROWS * FFD];    // FFN hidden

// ---------------- helpers ---------------------------------------------------
__device__ __forceinline__ uint32_t smem_u32(const void* p) {
    return (uint32_t)__cvta_generic_to_shared(p);
}

__device__ __forceinline__ uint32_t pack_h2(float lo, float hi) {
    __half2 p = __floats2half2_rn(lo, hi);
    return *reinterpret_cast<uint32_t*>(&p);
}

__device__ __forceinline__ void cp16(uint32_t dst, const void* src) {
    asm volatile("cp.async.cg.shared.global [%0], [%1], 16;" :: "r"(dst), "l"(src));
}
#define CP_COMMIT() asm volatile("cp.async.commit_group;" ::: "memory")
#define CP_WAIT1()  asm volatile("cp.async.wait_group 1;" ::: "memory")
#define CP_WAIT0()  asm volatile("cp.async.wait_group 0;" ::: "memory")

__device__ __forceinline__ void mma_f16(float* c, const uint32_t* a, const uint32_t* b) {
    asm volatile(
        "mma.sync.aligned.m16n8k16.row.col.f32.f16.f16.f32 "
        "{%0,%1,%2,%3}, {%4,%5,%6,%7}, {%8,%9}, {%0,%1,%2,%3};"
        : "+f"(c[0]), "+f"(c[1]), "+f"(c[2]), "+f"(c[3])
        : "r"(a[0]), "r"(a[1]), "r"(a[2]), "r"(a[3]), "r"(b[0]), "r"(b[1]));
}

__device__ __forceinline__ void ldsm_x4(uint32_t* r, uint32_t addr) {
    asm volatile("ldmatrix.sync.aligned.m8n8.x4.shared.b16 {%0,%1,%2,%3}, [%4];"
        : "=r"(r[0]), "=r"(r[1]), "=r"(r[2]), "=r"(r[3]) : "r"(addr));
}
__device__ __forceinline__ void ldsm_x2(uint32_t* r, uint32_t addr) {
    asm volatile("ldmatrix.sync.aligned.m8n8.x2.shared.b16 {%0,%1}, [%2];"
        : "=r"(r[0]), "=r"(r[1]) : "r"(addr));
}
__device__ __forceinline__ void ldsm_x2_trans(uint32_t* r, uint32_t addr) {
    asm volatile("ldmatrix.sync.aligned.m8n8.x2.trans.shared.b16 {%0,%1}, [%2];"
        : "=r"(r[0]), "=r"(r[1]) : "r"(addr));
}

__device__ __forceinline__ float gelu_exact(float v) {
    return 0.5f * v * (1.0f + erff(v * 0.70710678118654752f));
}

// ---------------- LayerNorm: warp-per-row, 8 rows per 256-thr block -------
__global__ __launch_bounds__(256) void ln_kernel(const float* __restrict__ x,
                                                 const float* __restrict__ gamma,
                                                 const float* __restrict__ beta,
                                                 __half* __restrict__ out) {
    int warp = threadIdx.x >> 5, lane = threadIdx.x & 31;
    int row = blockIdx.x * 8 + warp;
    const float* xr = x + (size_t)row * DD;

    float4 v[8];
    float s = 0.f;
#pragma unroll
    for (int k = 0; k < 8; ++k) {
        v[k] = *(const float4*)(xr + k * 128 + lane * 4);
        s += v[k].x + v[k].y + v[k].z + v[k].w;
    }
#pragma unroll
    for (int off = 16; off; off >>= 1) s += __shfl_xor_sync(0xffffffffu, s, off);
    float mean = s * (1.0f / DD);

    float sq = 0.f;
#pragma unroll
    for (int k = 0; k < 8; ++k) {
        float dx = v[k].x - mean, dy = v[k].y - mean;
        float dz = v[k].z - mean, dw = v[k].w - mean;
        sq += dx * dx + dy * dy + dz * dz + dw * dw;
    }
#pragma unroll
    for (int off = 16; off; off >>= 1) sq += __shfl_xor_sync(0xffffffffu, sq, off);
    float rstd = rsqrtf(sq * (1.0f / DD) + 1e-5f);

#pragma unroll
    for (int k = 0; k < 8; ++k) {
        float4 g4 = *(const float4*)(gamma + k * 128 + lane * 4);
        float4 b4 = *(const float4*)(beta + k * 128 + lane * 4);
        uint2 o;
        o.x = pack_h2((v[k].x - mean) * rstd * g4.x + b4.x,
                      (v[k].y - mean) * rstd * g4.y + b4.y);
        o.y = pack_h2((v[k].z - mean) * rstd * g4.z + b4.z,
                      (v[k].w - mean) * rstd * g4.w + b4.w);
        *(uint2*)(out + (size_t)row * DD + k * 128 + lane * 4) = o;
    }
}

// ---------------- pack wq/wk/wv [H,D,DH] -> [3072 (N), 1024 (K)] fp16 -----
__global__ __launch_bounds__(256) void repack_wqkv(const float* __restrict__ wq,
                                                   const float* __restrict__ wk,
                                                   const float* __restrict__ wv,
                                                   __half* __restrict__ wt) {
    __shared__ float t[32][33];
    int part = blockIdx.z >> 4, h = blockIdx.z & 15;
    int db = blockIdx.y * 32;
    int eb = blockIdx.x * 32;
    const float* w = (part == 0) ? wq : (part == 1) ? wk : wv;
    const float* wb = w + ((size_t)h * DD + db) * DHH + eb;
#pragma unroll
    for (int i = 0; i < 32; i += 8)
        t[threadIdx.y + i][threadIdx.x] = wb[(size_t)(threadIdx.y + i) * DHH + threadIdx.x];
    __syncthreads();
    float scale = (part == 0) ? 0.125f : 1.0f;
    int nbase = part * DD + h * DHH + eb;
#pragma unroll
    for (int i = 0; i < 32; i += 8)
        wt[(size_t)(nbase + threadIdx.y + i) * DD + db + threadIdx.x] =
            __float2half_rn(t[threadIdx.x][threadIdx.y + i] * scale);
}

// ---------------- transpose [R,C] fp32 -> [C,R] fp16 ----------------------
__global__ __launch_bounds__(256) void transpose_kernel(const float* __restrict__ in,
                                                        __half* __restrict__ out,
                                                        int R, int C) {
    __shared__ float t[32][33];
    int rb = blockIdx.y * 32, cb = blockIdx.x * 32;
#pragma unroll
    for (int i = 0; i < 32; i += 8)
        t[threadIdx.y + i][threadIdx.x] = in[(size_t)(rb + threadIdx.y + i) * C + cb + threadIdx.x];
    __syncthreads();
#pragma unroll
    for (int i = 0; i < 32; i += 8)
        out[(size_t)(cb + threadIdx.y + i) * R + rb + threadIdx.x] =
            __float2half_rn(t[threadIdx.x][threadIdx.y + i]);
}

// ---------------- fp16 mma.sync GEMM: C[M,N] = A[M,K] @ Wt[N,K]^T ---------
// CTA tile 128x128, 8 warps (2x4), warp tile 64x32. Fragment feed via
// ldmatrix (A: x4 per mt; B: x4 per nt-pair). Next-stage cp.async issued
// right after the barrier so global loads overlap the full compute block.
#define APAD 36                                   // uint32 per row (144B)
#define HALF_U 4608
#define STAGE_U 9216
#define NSTG 3
#define GEMM_SMEM (NSTG * STAGE_U * 4)            // 110592 bytes (2 CTAs/SM)

template<int EPI>
__global__ __launch_bounds__(256)
void gemm_f16_kernel(const __half* __restrict__ A,
                     const __half* __restrict__ Wt,
                     void* __restrict__ Cv,
                     const float* __restrict__ bias, const float* __restrict__ res,
                     int M, int N, int K) {
    extern __shared__ uint32_t smem[];
    uint32_t sbase = smem_u32(smem);
    int tid = threadIdx.x;
    int wid = tid >> 5, lane = tid & 31;
    int g = lane >> 2, t = lane & 3;
    int l8 = lane & 7, mi = lane >> 3;
    int warp_m = wid >> 2, warp_n = wid & 3;
    int m0 = blockIdx.y << 7, n0 = blockIdx.x << 7;

    const __half* Ab = A + (size_t)m0 * K;
    const __half* Bb = Wt + (size_t)n0 * K;
    int kt = K >> 6;

    float acc[4][4][4] = {};

    uint32_t lm_off = (uint32_t)((((mi & 1) << 3) + l8) * 144 + ((mi >> 1) << 4));

    auto load_stage = [&](int s, int jt) {
        uint32_t sA = sbase + s * STAGE_U * 4;
        uint32_t sB = sA + HALF_U * 4;
        int k0 = jt << 6;
#pragma unroll
        for (int i = 0; i < 4; ++i) {
            int f = i * 256 + tid;
            int row = f >> 3, ch = f & 7;
            uint32_t doff = (uint32_t)(row * 144 + ch * 16);
            cp16(sA + doff, Ab + (size_t)row * K + k0 + ch * 8);
            cp16(sB + doff, Bb + (size_t)row * K + k0 + ch * 8);
        }
    };

#pragma unroll
    for (int s = 0; s < NSTG - 1; ++s) { load_stage(s, s); CP_COMMIT(); }

    for (int j = 0; j < kt; ++j) {
        CP_WAIT1();
        __syncthreads();
        // issue next-stage loads FIRST so they overlap this epoch's compute.
        // stage (j+2)%3 was last read in iteration j-1; the barrier above
        // orders those reads before these writes.
        if (j + NSTG - 1 < kt) load_stage((j + NSTG - 1) % NSTG, j + NSTG - 1);
        CP_COMMIT();

        uint32_t sAu = sbase + (j % NSTG) * STAGE_U * 4;
        uint32_t sBu = sAu + HALF_U * 4;
#pragma unroll
        for (int ks = 0; ks < 4; ++ks) {
            uint32_t kboff = (uint32_t)(ks * 32);
            uint32_t a[4][4], b[4][2];
#pragma unroll
            for (int mt = 0; mt < 4; ++mt)
                ldsm_x4(a[mt], sAu + (uint32_t)((warp_m * 64 + mt * 16) * 144)
                               + kboff + lm_off);
#pragma unroll
            for (int ntp = 0; ntp < 2; ++ntp) {
                uint32_t r[4];
                ldsm_x4(r, sBu + (uint32_t)((warp_n * 32 + ntp * 16) * 144)
                           + kboff + lm_off);
                b[2 * ntp][0]     = r[0]; b[2 * ntp][1]     = r[2];
                b[2 * ntp + 1][0] = r[1]; b[2 * ntp + 1][1] = r[3];
            }
#pragma unroll
            for (int mt = 0; mt < 4; ++mt)
#pragma unroll
                for (int nt = 0; nt < 4; ++nt)
                    mma_f16(acc[mt][nt], a[mt], b[nt]);
        }
    }

#pragma unroll
    for (int mt = 0; mt < 4; ++mt) {
#pragma unroll
        for (int nt = 0; nt < 4; ++nt) {
#pragma unroll
            for (int half = 0; half < 2; ++half) {
                int row = m0 + warp_m * 64 + mt * 16 + g + half * 8;
                int col = n0 + warp_n * 32 + nt * 8 + 2 * t;
                float v0 = acc[mt][nt][half * 2 + 0];
                float v1 = acc[mt][nt][half * 2 + 1];
                size_t ga = (size_t)row * N + col;
                if (EPI == 0) {
                    *(uint32_t*)((__half*)Cv + ga) = pack_h2(v0, v1);
                } else if (EPI == 2) {
                    v0 = gelu_exact(v0 + bias[col]);
                    v1 = gelu_exact(v1 + bias[col + 1]);
                    *(uint32_t*)((__half*)Cv + ga) = pack_h2(v0, v1);
                } else {
                    float2 r = *(const float2*)(res + ga);
                    if (EPI == 3) { v0 += bias[col]; v1 += bias[col + 1]; }
                    float2 o; o.x = v0 + r.x; o.y = v1 + r.y;
                    *(float2*)((float*)Cv + ga) = o;
                }
            }
        }
    }
}

// ---------------- Flash attention (causal), fp16 mma + ldmatrix + cp.async --
#define FA_Q_U    4608                       // 128*36
#define FA_KV_U   2304                       // 64*36
#define FA_STG_U  (2 * FA_KV_U)              // 4608 (K then V)
#define FA_SMEM   ((FA_Q_U + 2 * FA_STG_U) * 4)   // 55296 bytes

__global__ __launch_bounds__(256) void flash_attn_mma_kernel(const __half* __restrict__ qkv,
                                                             __half* __restrict__ attn) {
    extern __shared__ uint32_t sm[];
    uint32_t sbase = smem_u32(sm);
    int tid = threadIdx.x;
    int wid = tid >> 5, lane = tid & 31;
    int g = lane >> 2, t = lane & 3;
    int l8 = lane & 7, l16 = lane & 15;
    int mi = lane >> 3;
    int qt = (int)gridDim.x - 1 - (int)blockIdx.x;   // longest-first scheduling
    int b = blockIdx.y >> 4, h = blockIdx.y & 15;
    int q0 = qt * 128;
    const __half* qbase = qkv + ((size_t)(b * SS + q0)) * (3 * DD) + h * DHH;
    const __half* kbase = qkv + ((size_t)(b * SS)) * (3 * DD) + DD + h * DHH;
    const __half* vbase = qkv + ((size_t)(b * SS)) * (3 * DD) + 2 * DD + h * DHH;

#pragma unroll
    for (int it = 0; it < 4; ++it) {
        int f = it * 256 + tid, r = f >> 3, ch = f & 7;
        uint4 v = *(const uint4*)(qbase + (size_t)r * (3 * DD) + ch * 8);
        *(uint4*)((char*)sm + r * 144 + ch * 16) = v;
    }

    int mrow = wid * 16;
    int ntiles = 2 * qt + 2;

    auto load_kv = [&](int s, int kt2) {
        uint32_t kvb = sbase + (FA_Q_U + s * FA_STG_U) * 4;
#pragma unroll
        for (int it = 0; it < 4; ++it) {
            int f = it * 256 + tid;
            int r = f >> 3, ch = f & 7;
            int key = kt2 * 64 + (r & 63);
            const __half* src = ((r < 64) ? kbase : vbase) + (size_t)key * (3 * DD) + ch * 8;
            uint32_t dst = kvb + ((r < 64) ? 0u : (uint32_t)(FA_KV_U * 4))
                         + (uint32_t)((r & 63) * 144 + ch * 16);
            cp16(dst, src);
        }
    };

    float acc_o[8][4] = {};
    float m0r = -INFINITY, m1r = -INFINITY, l0r = 0.f, l1r = 0.f;

    load_kv(0, 0);
    CP_COMMIT();

    for (int kt = 0; kt < ntiles; ++kt) {
        int cur = kt & 1;
        uint32_t ksb = sbase + (FA_Q_U + cur * FA_STG_U) * 4;
        uint32_t vsb = ksb + FA_KV_U * 4;
        CP_WAIT0();
        __syncthreads();
        if (kt + 1 < ntiles) load_kv((kt + 1) & 1, kt + 1);
        CP_COMMIT();

        float acc_s[8][4] = {};
#pragma unroll
        for (int ks = 0; ks < 4; ++ks) {
            uint32_t aq[4];
            uint32_t qaddr = sbase + (uint32_t)((mrow + ((mi & 1) << 3) + l8) * 144
                                                + ks * 32 + ((mi >> 1) << 4));
            ldsm_x4(aq, qaddr);
#pragma unroll
            for (int nt = 0; nt < 8; ++nt) {
                uint32_t bk[2];
                uint32_t kaddr = ksb + (uint32_t)((nt * 8 + l8) * 144
                                                  + ks * 32 + (((lane >> 3) & 1) << 4));
                ldsm_x2(bk, kaddr);
                mma_f16(acc_s[nt], aq, bk);
            }
        }

        if (kt >= 2 * qt) {
            int r0 = q0 + mrow + g, r1 = r0 + 8;
#pragma unroll
            for (int nt = 0; nt < 8; ++nt) {
                int c0 = kt * 64 + nt * 8 + 2 * t;
                if (c0     > r0) acc_s[nt][0] = -INFINITY;
                if (c0 + 1 > r0) acc_s[nt][1] = -INFINITY;
                if (c0     > r1) acc_s[nt][2] = -INFINITY;
                if (c0 + 1 > r1) acc_s[nt][3] = -INFINITY;
            }
        }

        float mx0 = -INFINITY, mx1 = -INFINITY;
#pragma unroll
        for (int nt = 0; nt < 8; ++nt) {
            mx0 = fmaxf(mx0, fmaxf(acc_s[nt][0], acc_s[nt][1]));
            mx1 = fmaxf(mx1, fmaxf(acc_s[nt][2], acc_s[nt][3]));
        }
        mx0 = fmaxf(mx0, __shfl_xor_sync(0xffffffffu, mx0, 1));
        mx0 = fmaxf(mx0, __shfl_xor_sync(0xffffffffu, mx0, 2));
        mx1 = fmaxf(mx1, __shfl_xor_sync(0xffffffffu, mx1, 1));
        mx1 = fmaxf(mx1, __shfl_xor_sync(0xffffffffu, mx1, 2));
        float mn0 = fmaxf(m0r, mx0), mn1 = fmaxf(m1r, mx1);
        float al0 = __expf(m0r - mn0), al1 = __expf(m1r - mn1);
        float rs0 = 0.f, rs1 = 0.f;
#pragma unroll
        for (int nt = 0; nt < 8; ++nt) {
            acc_s[nt][0] = __expf(acc_s[nt][0] - mn0);
            acc_s[nt][1] = __expf(acc_s[nt][1] - mn0);
            acc_s[nt][2] = __expf(acc_s[nt][2] - mn1);
            acc_s[nt][3] = __expf(acc_s[nt][3] - mn1);
            rs0 += acc_s[nt][0] + acc_s[nt][1];
            rs1 += acc_s[nt][2] + acc_s[nt][3];
        }
        rs0 += __shfl_xor_sync(0xffffffffu, rs0, 1);
        rs0 += __shfl_xor_sync(0xffffffffu, rs0, 2);
        rs1 += __shfl_xor_sync(0xffffffffu, rs1, 1);
        rs1 += __shfl_xor_sync(0xffffffffu, rs1, 2);
        l0r = l0r * al0 + rs0;  m0r = mn0;
        l1r = l1r * al1 + rs1;  m1r = mn1;
#pragma unroll
        for (int nt = 0; nt < 8; ++nt) {
            acc_o[nt][0] *= al0; acc_o[nt][1] *= al0;
            acc_o[nt][2] *= al1; acc_o[nt][3] *= al1;
        }

#pragma unroll
        for (int ks = 0; ks < 4; ++ks) {
            uint32_t ap[4];
            ap[0] = pack_h2(acc_s[2 * ks][0],     acc_s[2 * ks][1]);
            ap[1] = pack_h2(acc_s[2 * ks][2],     acc_s[2 * ks][3]);
            ap[2] = pack_h2(acc_s[2 * ks + 1][0], acc_s[2 * ks + 1][1]);
            ap[3] = pack_h2(acc_s[2 * ks + 1][2], acc_s[2 * ks + 1][3]);
            uint32_t vrow = vsb + (uint32_t)((ks * 16 + l16) * 144);
#pragma unroll
            for (int nt = 0; nt < 8; ++nt) {
                uint32_t bv[2];
                ldsm_x2_trans(bv, vrow + (uint32_t)(nt * 16));
                mma_f16(acc_o[nt], ap, bv);
            }
        }
    }

    float inv0 = 1.0f / l0r, inv1 = 1.0f / l1r;
    int r0 = q0 + mrow + g, r1 = r0 + 8;
#pragma unroll
    for (int nt = 0; nt < 8; ++nt) {
        int col = h * DHH + nt * 8 + 2 * t;
        *(uint32_t*)(attn + ((size_t)(b * SS + r0)) * DD + col) =
            pack_h2(acc_o[nt][0] * inv0, acc_o[nt][1] * inv0);
        *(uint32_t*)(attn + ((size_t)(b * SS + r1)) * DD + col) =
            pack_h2(acc_o[nt][2] * inv1, acc_o[nt][3] * inv1);
    }
}

// ---------------- launch ---------------------------------------------------
extern "C" void kernel_launch(void* const* d_in, const int* in_sizes, int n_in,
                              void* d_out, int out_size) {
    const float* x   = (const float*)d_in[0];
    const float* wq  = (const float*)d_in[2];
    const float* wk  = (const float*)d_in[3];
    const float* wv  = (const float*)d_in[4];
    const float* wo  = (const float*)d_in[5];
    const float* w1  = (const float*)d_in[6];
    const float* b1  = (const float*)d_in[7];
    const float* w2  = (const float*)d_in[8];
    const float* b2  = (const float*)d_in[9];
    const float* g1  = (const float*)d_in[10];
    const float* be1 = (const float*)d_in[11];
    const float* g2  = (const float*)d_in[12];
    const float* be2 = (const float*)d_in[13];
    float* out = (float*)d_out;

    __half *h, *h2, *wqkv, *wot, *w1t, *w2t, *qkv, *attn, *ff1;
    cudaGetSymbolAddress((void**)&h,    g_h);
    cudaGetSymbolAddress((void**)&h2,   g_h2);
    cudaGetSymbolAddress((void**)&wqkv, g_wqkv);
    cudaGetSymbolAddress((void**)&wot,  g_wot);
    cudaGetSymbolAddress((void**)&w1t,  g_w1t);
    cudaGetSymbolAddress((void**)&w2t,  g_w2t);
    cudaGetSymbolAddress((void**)&qkv,  g_qkv);
    cudaGetSymbolAddress((void**)&attn, g_attn);
    cudaGetSymbolAddress((void**)&ff1,  g_ff1);

    cudaFuncSetAttribute(gemm_f16_kernel<0>, cudaFuncAttributeMaxDynamicSharedMemorySize, GEMM_SMEM);
    cudaFuncSetAttribute(gemm_f16_kernel<1>, cudaFuncAttributeMaxDynamicSharedMemorySize, GEMM_SMEM);
    cudaFuncSetAttribute(gemm_f16_kernel<2>, cudaFuncAttributeMaxDynamicSharedMemorySize, GEMM_SMEM);
    cudaFuncSetAttribute(gemm_f16_kernel<3>, cudaFuncAttributeMaxDynamicSharedMemorySize, GEMM_SMEM);
    cudaFuncSetAttribute(flash_attn_mma_kernel, cudaFuncAttributeMaxDynamicSharedMemorySize, FA_SMEM);

    // weight repacks (per-launch, coalesced)
    repack_wqkv<<<dim3(2, 32, 48), dim3(32, 8)>>>(wq, wk, wv, wqkv);
    transpose_kernel<<<dim3(DD / 32, DD / 32),  dim3(32, 8)>>>(wo, wot, DD, DD);
    transpose_kernel<<<dim3(FFD / 32, DD / 32), dim3(32, 8)>>>(w1, w1t, DD, FFD);
    transpose_kernel<<<dim3(DD / 32, FFD / 32), dim3(32, 8)>>>(w2, w2t, FFD, DD);

    // 1. LN1 (fp16 out)
    ln_kernel<<<NROWS / 8, 256>>>(x, g1, be1, h);
    // 2. QKV projection: [8192,1024] @ [1024,3072] -> fp16
    gemm_f16_kernel<0><<<dim3(3 * DD / 128, NROWS / 128), 256, GEMM_SMEM>>>(
        h, wqkv, qkv, nullptr, nullptr, NROWS, 3 * DD, DD);
    // 3. flash attention
    flash_attn_mma_kernel<<<dim3(SS / 128, BB * HH), 256, FA_SMEM>>>(qkv, attn);
    // 4. out = x + attn @ wo   (fp32 out)
    gemm_f16_kernel<1><<<dim3(DD / 128, NROWS / 128), 256, GEMM_SMEM>>>(
        attn, wot, out, nullptr, x, NROWS, DD, DD);
    // 5. LN2 (fp16 out)
    ln_kernel<<<NROWS / 8, 256>>>(out, g2, be2, h2);
    // 6. ff1 = gelu(h2 @ w1 + b1)  -> fp16
    gemm_f16_kernel<2><<<dim3(FFD / 128, NROWS / 128), 256, GEMM_SMEM>>>(
        h2, w1t, ff1, b1, nullptr, NROWS, FFD, DD);
    // 7. out = out + ff1 @ w2 + b2   (fp32, in-place residual)
    gemm_f16_kernel<3><<<dim3(DD / 128, NROWS / 128), 256, GEMM_SMEM>>>(
        ff1, w2t, out, b2, out, NROWS, DD, FFD);
}

// round 17
// speedup vs baseline: 1.1071x; 1.0278x over previous
#include <cuda_runtime.h>
#include <cuda_fp16.h>
#include <math.h>
#include <stdint.h>

// Problem constants
#define BB 4
#define SS 2048
#define DD 1024
#define HH 16
#define DHH 64
#define FFD 4096
#define NROWS (BB*SS)          // 8192

// ---------------- scratch (device globals: allocation-guard safe) ----------
__device__ __half g_h   [(size_t)NROWS * DD];     // LN1 out
__device__ __half g_h2  [(size_t)NROWS * DD];     // LN2 out
__device__ __half g_wqkv[(size_t)3 * DD * DD];    // [3072 (N), 1024 (K)], q-part pre-scaled 0.125
__device__ __half g_wot [(size_t)DD * DD];        // wo^T
__device__ __half g_w1t [(size_t)FFD * DD];       // w1^T
__device__ __half g_w2t [(size_t)DD * FFD];       // w2^T
__device__ __half g_qkv [(size_t)NROWS * 3 * DD]; // [8192, 3072]
__device__ __half g_attn[(size_t)NROWS * DD];     // attention out
__device__ __half g_ff1 [(size_t)NROWS * FFD];    // FFN hidden

// ---------------- helpers ---------------------------------------------------
__device__ __forceinline__ uint32_t smem_u32(const void* p) {
    return (uint32_t)__cvta_generic_to_shared(p);
}

__device__ __forceinline__ uint32_t pack_h2(float lo, float hi) {
    __half2 p = __floats2half2_rn(lo, hi);
    return *reinterpret_cast<uint32_t*>(&p);
}

__device__ __forceinline__ void cp16(uint32_t dst, const void* src) {
    asm volatile("cp.async.cg.shared.global [%0], [%1], 16;" :: "r"(dst), "l"(src));
}
#define CP_COMMIT() asm volatile("cp.async.commit_group;" ::: "memory")
#define CP_WAIT1()  asm volatile("cp.async.wait_group 1;" ::: "memory")
#define CP_WAIT0()  asm volatile("cp.async.wait_group 0;" ::: "memory")

__device__ __forceinline__ void mma_f16(float* c, const uint32_t* a, const uint32_t* b) {
    asm volatile(
        "mma.sync.aligned.m16n8k16.row.col.f32.f16.f16.f32 "
        "{%0,%1,%2,%3}, {%4,%5,%6,%7}, {%8,%9}, {%0,%1,%2,%3};"
        : "+f"(c[0]), "+f"(c[1]), "+f"(c[2]), "+f"(c[3])
        : "r"(a[0]), "r"(a[1]), "r"(a[2]), "r"(a[3]), "r"(b[0]), "r"(b[1]));
}

__device__ __forceinline__ void ldsm_x4(uint32_t* r, uint32_t addr) {
    asm volatile("ldmatrix.sync.aligned.m8n8.x4.shared.b16 {%0,%1,%2,%3}, [%4];"
        : "=r"(r[0]), "=r"(r[1]), "=r"(r[2]), "=r"(r[3]) : "r"(addr));
}
__device__ __forceinline__ void ldsm_x2(uint32_t* r, uint32_t addr) {
    asm volatile("ldmatrix.sync.aligned.m8n8.x2.shared.b16 {%0,%1}, [%2];"
        : "=r"(r[0]), "=r"(r[1]) : "r"(addr));
}
__device__ __forceinline__ void ldsm_x2_trans(uint32_t* r, uint32_t addr) {
    asm volatile("ldmatrix.sync.aligned.m8n8.x2.trans.shared.b16 {%0,%1}, [%2];"
        : "=r"(r[0]), "=r"(r[1]) : "r"(addr));
}

__device__ __forceinline__ float gelu_exact(float v) {
    return 0.5f * v * (1.0f + erff(v * 0.70710678118654752f));
}

// ---------------- LayerNorm: warp-per-row, 8 rows per 256-thr block -------
__global__ __launch_bounds__(256) void ln_kernel(const float* __restrict__ x,
                                                 const float* __restrict__ gamma,
                                                 const float* __restrict__ beta,
                                                 __half* __restrict__ out) {
    int warp = threadIdx.x >> 5, lane = threadIdx.x & 31;
    int row = blockIdx.x * 8 + warp;
    const float* xr = x + (size_t)row * DD;

    float4 v[8];
    float s = 0.f;
#pragma unroll
    for (int k = 0; k < 8; ++k) {
        v[k] = *(const float4*)(xr + k * 128 + lane * 4);
        s += v[k].x + v[k].y + v[k].z + v[k].w;
    }
#pragma unroll
    for (int off = 16; off; off >>= 1) s += __shfl_xor_sync(0xffffffffu, s, off);
    float mean = s * (1.0f / DD);

    float sq = 0.f;
#pragma unroll
    for (int k = 0; k < 8; ++k) {
        float dx = v[k].x - mean, dy = v[k].y - mean;
        float dz = v[k].z - mean, dw = v[k].w - mean;
        sq += dx * dx + dy * dy + dz * dz + dw * dw;
    }
#pragma unroll
    for (int off = 16; off; off >>= 1) sq += __shfl_xor_sync(0xffffffffu, sq, off);
    float rstd = rsqrtf(sq * (1.0f / DD) + 1e-5f);

#pragma unroll
    for (int k = 0; k < 8; ++k) {
        float4 g4 = *(const float4*)(gamma + k * 128 + lane * 4);
        float4 b4 = *(const float4*)(beta + k * 128 + lane * 4);
        uint2 o;
        o.x = pack_h2((v[k].x - mean) * rstd * g4.x + b4.x,
                      (v[k].y - mean) * rstd * g4.y + b4.y);
        o.y = pack_h2((v[k].z - mean) * rstd * g4.z + b4.z,
                      (v[k].w - mean) * rstd * g4.w + b4.w);
        *(uint2*)(out + (size_t)row * DD + k * 128 + lane * 4) = o;
    }
}

// ---------------- pack wq/wk/wv [H,D,DH] -> [3072 (N), 1024 (K)] fp16 -----
__global__ __launch_bounds__(256) void repack_wqkv(const float* __restrict__ wq,
                                                   const float* __restrict__ wk,
                                                   const float* __restrict__ wv,
                                                   __half* __restrict__ wt) {
    __shared__ float t[32][33];
    int part = blockIdx.z >> 4, h = blockIdx.z & 15;
    int db = blockIdx.y * 32;
    int eb = blockIdx.x * 32;
    const float* w = (part == 0) ? wq : (part == 1) ? wk : wv;
    const float* wb = w + ((size_t)h * DD + db) * DHH + eb;
#pragma unroll
    for (int i = 0; i < 32; i += 8)
        t[threadIdx.y + i][threadIdx.x] = wb[(size_t)(threadIdx.y + i) * DHH + threadIdx.x];
    __syncthreads();
    float scale = (part == 0) ? 0.125f : 1.0f;
    int nbase = part * DD + h * DHH + eb;
#pragma unroll
    for (int i = 0; i < 32; i += 8)
        wt[(size_t)(nbase + threadIdx.y + i) * DD + db + threadIdx.x] =
            __float2half_rn(t[threadIdx.x][threadIdx.y + i] * scale);
}

// ---------------- batched transpose of wo/w1/w2 -> fp16 -------------------
// Linearized tiles: [0,1024) wo [1024x1024], [1024,5120) w1 [1024x4096],
// [5120,9216) w2 [4096x1024]. Each tile is 32x32.
__global__ __launch_bounds__(256) void transpose3_kernel(const float* __restrict__ wo,
                                                         const float* __restrict__ w1,
                                                         const float* __restrict__ w2,
                                                         __half* __restrict__ wot,
                                                         __half* __restrict__ w1t,
                                                         __half* __restrict__ w2t) {
    __shared__ float t[32][33];
    int idx = blockIdx.x;
    const float* in; __half* out; int R, C, tile;
    if (idx < 1024)      { in = wo; out = wot; R = DD;  C = DD;  tile = idx; }
    else if (idx < 5120) { in = w1; out = w1t; R = DD;  C = FFD; tile = idx - 1024; }
    else                 { in = w2; out = w2t; R = FFD; C = DD;  tile = idx - 5120; }
    int ctiles = C >> 5;
    int rb = (tile / ctiles) << 5, cb = (tile % ctiles) << 5;
#pragma unroll
    for (int i = 0; i < 32; i += 8)
        t[threadIdx.y + i][threadIdx.x] = in[(size_t)(rb + threadIdx.y + i) * C + cb + threadIdx.x];
    __syncthreads();
#pragma unroll
    for (int i = 0; i < 32; i += 8)
        out[(size_t)(cb + threadIdx.y + i) * R + rb + threadIdx.x] =
            __float2half_rn(t[threadIdx.x][threadIdx.y + i]);
}

// ---------------- fp16 mma.sync GEMM: C[M,N] = A[M,K] @ Wt[N,K]^T ---------
// CTA tile 128x128, 8 warps (2x4), warp tile 64x32. Fragment feed via
// ldmatrix (A: x4 per mt; B: x4 per nt-pair). Next-stage cp.async issued
// AFTER the compute block (R13 ordering — verified fastest).
#define APAD 36                                   // uint32 per row (144B)
#define HALF_U 4608
#define STAGE_U 9216
#define NSTG 3
#define GEMM_SMEM (NSTG * STAGE_U * 4)            // 110592 bytes (2 CTAs/SM)

template<int EPI>
__global__ __launch_bounds__(256)
void gemm_f16_kernel(const __half* __restrict__ A,
                     const __half* __restrict__ Wt,
                     void* __restrict__ Cv,
                     const float* __restrict__ bias, const float* __restrict__ res,
                     int M, int N, int K) {
    extern __shared__ uint32_t smem[];
    uint32_t sbase = smem_u32(smem);
    int tid = threadIdx.x;
    int wid = tid >> 5, lane = tid & 31;
    int g = lane >> 2, t = lane & 3;
    int l8 = lane & 7, mi = lane >> 3;
    int warp_m = wid >> 2, warp_n = wid & 3;
    int m0 = blockIdx.y << 7, n0 = blockIdx.x << 7;

    const __half* Ab = A + (size_t)m0 * K;
    const __half* Bb = Wt + (size_t)n0 * K;
    int kt = K >> 6;

    float acc[4][4][4] = {};

    uint32_t lm_off = (uint32_t)((((mi & 1) << 3) + l8) * 144 + ((mi >> 1) << 4));

    auto load_stage = [&](int s, int jt) {
        uint32_t sA = sbase + s * STAGE_U * 4;
        uint32_t sB = sA + HALF_U * 4;
        int k0 = jt << 6;
#pragma unroll
        for (int i = 0; i < 4; ++i) {
            int f = i * 256 + tid;
            int row = f >> 3, ch = f & 7;
            uint32_t doff = (uint32_t)(row * 144 + ch * 16);
            cp16(sA + doff, Ab + (size_t)row * K + k0 + ch * 8);
            cp16(sB + doff, Bb + (size_t)row * K + k0 + ch * 8);
        }
    };

#pragma unroll
    for (int s = 0; s < NSTG - 1; ++s) { load_stage(s, s); CP_COMMIT(); }

    for (int j = 0; j < kt; ++j) {
        CP_WAIT1();
        __syncthreads();
        uint32_t sAu = sbase + (j % NSTG) * STAGE_U * 4;
        uint32_t sBu = sAu + HALF_U * 4;
#pragma unroll
        for (int ks = 0; ks < 4; ++ks) {
            uint32_t kboff = (uint32_t)(ks * 32);
            uint32_t a[4][4], b[4][2];
#pragma unroll
            for (int mt = 0; mt < 4; ++mt)
                ldsm_x4(a[mt], sAu + (uint32_t)((warp_m * 64 + mt * 16) * 144)
                               + kboff + lm_off);
#pragma unroll
            for (int ntp = 0; ntp < 2; ++ntp) {
                uint32_t r[4];
                ldsm_x4(r, sBu + (uint32_t)((warp_n * 32 + ntp * 16) * 144)
                           + kboff + lm_off);
                b[2 * ntp][0]     = r[0]; b[2 * ntp][1]     = r[2];
                b[2 * ntp + 1][0] = r[1]; b[2 * ntp + 1][1] = r[3];
            }
#pragma unroll
            for (int mt = 0; mt < 4; ++mt)
#pragma unroll
                for (int nt = 0; nt < 4; ++nt)
                    mma_f16(acc[mt][nt], a[mt], b[nt]);
        }
        if (j + NSTG - 1 < kt) load_stage((j + NSTG - 1) % NSTG, j + NSTG - 1);
        CP_COMMIT();
    }

#pragma unroll
    for (int mt = 0; mt < 4; ++mt) {
#pragma unroll
        for (int nt = 0; nt < 4; ++nt) {
#pragma unroll
            for (int half = 0; half < 2; ++half) {
                int row = m0 + warp_m * 64 + mt * 16 + g + half * 8;
                int col = n0 + warp_n * 32 + nt * 8 + 2 * t;
                float v0 = acc[mt][nt][half * 2 + 0];
                float v1 = acc[mt][nt][half * 2 + 1];
                size_t ga = (size_t)row * N + col;
                if (EPI == 0) {
                    *(uint32_t*)((__half*)Cv + ga) = pack_h2(v0, v1);
                } else if (EPI == 2) {
                    v0 = gelu_exact(v0 + bias[col]);
                    v1 = gelu_exact(v1 + bias[col + 1]);
                    *(uint32_t*)((__half*)Cv + ga) = pack_h2(v0, v1);
                } else {
                    float2 r = *(const float2*)(res + ga);
                    if (EPI == 3) { v0 += bias[col]; v1 += bias[col + 1]; }
                    float2 o; o.x = v0 + r.x; o.y = v1 + r.y;
                    *(float2*)((float*)Cv + ga) = o;
                }
            }
        }
    }
}

// ---------------- Flash attention (causal), fp16 mma + ldmatrix + cp.async --
#define FA_Q_U    4608                       // 128*36
#define FA_KV_U   2304                       // 64*36
#define FA_STG_U  (2 * FA_KV_U)              // 4608 (K then V)
#define FA_SMEM   ((FA_Q_U + 2 * FA_STG_U) * 4)   // 55296 bytes

__global__ __launch_bounds__(256) void flash_attn_mma_kernel(const __half* __restrict__ qkv,
                                                             __half* __restrict__ attn) {
    extern __shared__ uint32_t sm[];
    uint32_t sbase = smem_u32(sm);
    int tid = threadIdx.x;
    int wid = tid >> 5, lane = tid & 31;
    int g = lane >> 2, t = lane & 3;
    int l8 = lane & 7, l16 = lane & 15;
    int mi = lane >> 3;
    int qt = (int)gridDim.x - 1 - (int)blockIdx.x;   // longest-first scheduling
    int b = blockIdx.y >> 4, h = blockIdx.y & 15;
    int q0 = qt * 128;
    const __half* qbase = qkv + ((size_t)(b * SS + q0)) * (3 * DD) + h * DHH;
    const __half* kbase = qkv + ((size_t)(b * SS)) * (3 * DD) + DD + h * DHH;
    const __half* vbase = qkv + ((size_t)(b * SS)) * (3 * DD) + 2 * DD + h * DHH;

#pragma unroll
    for (int it = 0; it < 4; ++it) {
        int f = it * 256 + tid, r = f >> 3, ch = f & 7;
        uint4 v = *(const uint4*)(qbase + (size_t)r * (3 * DD) + ch * 8);
        *(uint4*)((char*)sm + r * 144 + ch * 16) = v;
    }

    int mrow = wid * 16;
    int ntiles = 2 * qt + 2;

    auto load_kv = [&](int s, int kt2) {
        uint32_t kvb = sbase + (FA_Q_U + s * FA_STG_U) * 4;
#pragma unroll
        for (int it = 0; it < 4; ++it) {
            int f = it * 256 + tid;
            int r = f >> 3, ch = f & 7;
            int key = kt2 * 64 + (r & 63);
            const __half* src = ((r < 64) ? kbase : vbase) + (size_t)key * (3 * DD) + ch * 8;
            uint32_t dst = kvb + ((r < 64) ? 0u : (uint32_t)(FA_KV_U * 4))
                         + (uint32_t)((r & 63) * 144 + ch * 16);
            cp16(dst, src);
        }
    };

    float acc_o[8][4] = {};
    float m0r = -INFINITY, m1r = -INFINITY, l0r = 0.f, l1r = 0.f;

    load_kv(0, 0);
    CP_COMMIT();

    for (int kt = 0; kt < ntiles; ++kt) {
        int cur = kt & 1;
        uint32_t ksb = sbase + (FA_Q_U + cur * FA_STG_U) * 4;
        uint32_t vsb = ksb + FA_KV_U * 4;
        CP_WAIT0();
        __syncthreads();
        if (kt + 1 < ntiles) load_kv((kt + 1) & 1, kt + 1);
        CP_COMMIT();

        float acc_s[8][4] = {};
#pragma unroll
        for (int ks = 0; ks < 4; ++ks) {
            uint32_t aq[4];
            uint32_t qaddr = sbase + (uint32_t)((mrow + ((mi & 1) << 3) + l8) * 144
                                                + ks * 32 + ((mi >> 1) << 4));
            ldsm_x4(aq, qaddr);
#pragma unroll
            for (int nt = 0; nt < 8; ++nt) {
                uint32_t bk[2];
                uint32_t kaddr = ksb + (uint32_t)((nt * 8 + l8) * 144
                                                  + ks * 32 + (((lane >> 3) & 1) << 4));
                ldsm_x2(bk, kaddr);
                mma_f16(acc_s[nt], aq, bk);
            }
        }

        if (kt >= 2 * qt) {
            int r0 = q0 + mrow + g, r1 = r0 + 8;
#pragma unroll
            for (int nt = 0; nt < 8; ++nt) {
                int c0 = kt * 64 + nt * 8 + 2 * t;
                if (c0     > r0) acc_s[nt][0] = -INFINITY;
                if (c0 + 1 > r0) acc_s[nt][1] = -INFINITY;
                if (c0     > r1) acc_s[nt][2] = -INFINITY;
                if (c0 + 1 > r1) acc_s[nt][3] = -INFINITY;
            }
        }

        float mx0 = -INFINITY, mx1 = -INFINITY;
#pragma unroll
        for (int nt = 0; nt < 8; ++nt) {
            mx0 = fmaxf(mx0, fmaxf(acc_s[nt][0], acc_s[nt][1]));
            mx1 = fmaxf(mx1, fmaxf(acc_s[nt][2], acc_s[nt][3]));
        }
        mx0 = fmaxf(mx0, __shfl_xor_sync(0xffffffffu, mx0, 1));
        mx0 = fmaxf(mx0, __shfl_xor_sync(0xffffffffu, mx0, 2));
        mx1 = fmaxf(mx1, __shfl_xor_sync(0xffffffffu, mx1, 1));
        mx1 = fmaxf(mx1, __shfl_xor_sync(0xffffffffu, mx1, 2));
        float mn0 = fmaxf(m0r, mx0), mn1 = fmaxf(m1r, mx1);
        float al0 = __expf(m0r - mn0), al1 = __expf(m1r - mn1);
        float rs0 = 0.f, rs1 = 0.f;
#pragma unroll
        for (int nt = 0; nt < 8; ++nt) {
            acc_s[nt][0] = __expf(acc_s[nt][0] - mn0);
            acc_s[nt][1] = __expf(acc_s[nt][1] - mn0);
            acc_s[nt][2] = __expf(acc_s[nt][2] - mn1);
            acc_s[nt][3] = __expf(acc_s[nt][3] - mn1);
            rs0 += acc_s[nt][0] + acc_s[nt][1];
            rs1 += acc_s[nt][2] + acc_s[nt][3];
        }
        rs0 += __shfl_xor_sync(0xffffffffu, rs0, 1);
        rs0 += __shfl_xor_sync(0xffffffffu, rs0, 2);
        rs1 += __shfl_xor_sync(0xffffffffu, rs1, 1);
        rs1 += __shfl_xor_sync(0xffffffffu, rs1, 2);
        l0r = l0r * al0 + rs0;  m0r = mn0;
        l1r = l1r * al1 + rs1;  m1r = mn1;
#pragma unroll
        for (int nt = 0; nt < 8; ++nt) {
            acc_o[nt][0] *= al0; acc_o[nt][1] *= al0;
            acc_o[nt][2] *= al1; acc_o[nt][3] *= al1;
        }

#pragma unroll
        for (int ks = 0; ks < 4; ++ks) {
            uint32_t ap[4];
            ap[0] = pack_h2(acc_s[2 * ks][0],     acc_s[2 * ks][1]);
            ap[1] = pack_h2(acc_s[2 * ks][2],     acc_s[2 * ks][3]);
            ap[2] = pack_h2(acc_s[2 * ks + 1][0], acc_s[2 * ks + 1][1]);
            ap[3] = pack_h2(acc_s[2 * ks + 1][2], acc_s[2 * ks + 1][3]);
            uint32_t vrow = vsb + (uint32_t)((ks * 16 + l16) * 144);
#pragma unroll
            for (int nt = 0; nt < 8; ++nt) {
                uint32_t bv[2];
                ldsm_x2_trans(bv, vrow + (uint32_t)(nt * 16));
                mma_f16(acc_o[nt], ap, bv);
            }
        }
    }

    float inv0 = 1.0f / l0r, inv1 = 1.0f / l1r;
    int r0 = q0 + mrow + g, r1 = r0 + 8;
#pragma unroll
    for (int nt = 0; nt < 8; ++nt) {
        int col = h * DHH + nt * 8 + 2 * t;
        *(uint32_t*)(attn + ((size_t)(b * SS + r0)) * DD + col) =
            pack_h2(acc_o[nt][0] * inv0, acc_o[nt][1] * inv0);
        *(uint32_t*)(attn + ((size_t)(b * SS + r1)) * DD + col) =
            pack_h2(acc_o[nt][2] * inv1, acc_o[nt][3] * inv1);
    }
}

// ---------------- launch ---------------------------------------------------
extern "C" void kernel_launch(void* const* d_in, const int* in_sizes, int n_in,
                              void* d_out, int out_size) {
    const float* x   = (const float*)d_in[0];
    const float* wq  = (const float*)d_in[2];
    const float* wk  = (const float*)d_in[3];
    const float* wv  = (const float*)d_in[4];
    const float* wo  = (const float*)d_in[5];
    const float* w1  = (const float*)d_in[6];
    const float* b1  = (const float*)d_in[7];
    const float* w2  = (const float*)d_in[8];
    const float* b2  = (const float*)d_in[9];
    const float* g1  = (const float*)d_in[10];
    const float* be1 = (const float*)d_in[11];
    const float* g2  = (const float*)d_in[12];
    const float* be2 = (const float*)d_in[13];
    float* out = (float*)d_out;

    __half *h, *h2, *wqkv, *wot, *w1t, *w2t, *qkv, *attn, *ff1;
    cudaGetSymbolAddress((void**)&h,    g_h);
    cudaGetSymbolAddress((void**)&h2,   g_h2);
    cudaGetSymbolAddress((void**)&wqkv, g_wqkv);
    cudaGetSymbolAddress((void**)&wot,  g_wot);
    cudaGetSymbolAddress((void**)&w1t,  g_w1t);
    cudaGetSymbolAddress((void**)&w2t,  g_w2t);
    cudaGetSymbolAddress((void**)&qkv,  g_qkv);
    cudaGetSymbolAddress((void**)&attn, g_attn);
    cudaGetSymbolAddress((void**)&ff1,  g_ff1);

    cudaFuncSetAttribute(gemm_f16_kernel<0>, cudaFuncAttributeMaxDynamicSharedMemorySize, GEMM_SMEM);
    cudaFuncSetAttribute(gemm_f16_kernel<1>, cudaFuncAttributeMaxDynamicSharedMemorySize, GEMM_SMEM);
    cudaFuncSetAttribute(gemm_f16_kernel<2>, cudaFuncAttributeMaxDynamicSharedMemorySize, GEMM_SMEM);
    cudaFuncSetAttribute(gemm_f16_kernel<3>, cudaFuncAttributeMaxDynamicSharedMemorySize, GEMM_SMEM);
    cudaFuncSetAttribute(flash_attn_mma_kernel, cudaFuncAttributeMaxDynamicSharedMemorySize, FA_SMEM);

    // weight repacks (per-launch, coalesced; transposes batched in one launch)
    repack_wqkv<<<dim3(2, 32, 48), dim3(32, 8)>>>(wq, wk, wv, wqkv);
    transpose3_kernel<<<9216, dim3(32, 8)>>>(wo, w1, w2, wot, w1t, w2t);

    // 1. LN1 (fp16 out)
    ln_kernel<<<NROWS / 8, 256>>>(x, g1, be1, h);
    // 2. QKV projection: [8192,1024] @ [1024,3072] -> fp16
    gemm_f16_kernel<0><<<dim3(3 * DD / 128, NROWS / 128), 256, GEMM_SMEM>>>(
        h, wqkv, qkv, nullptr, nullptr, NROWS, 3 * DD, DD);
    // 3. flash attention
    flash_attn_mma_kernel<<<dim3(SS / 128, BB * HH), 256, FA_SMEM>>>(qkv, attn);
    // 4. out = x + attn @ wo   (fp32 out)
    gemm_f16_kernel<1><<<dim3(DD / 128, NROWS / 128), 256, GEMM_SMEM>>>(
        attn, wot, out, nullptr, x, NROWS, DD, DD);
    // 5. LN2 (fp16 out)
    ln_kernel<<<NROWS / 8, 256>>>(out, g2, be2, h2);
    // 6. ff1 = gelu(h2 @ w1 + b1)  -> fp16
    gemm_f16_kernel<2><<<dim3(FFD / 128, NROWS / 128), 256, GEMM_SMEM>>>(
        h2, w1t, ff1, b1, nullptr, NROWS, FFD, DD);
    // 7. out = out + ff1 @ w2 + b2   (fp32, in-place residual)
    gemm_f16_kernel<3><<<dim3(DD / 128, NROWS / 128), 256, GEMM_SMEM>>>(
        ff1, w2t, out, b2, out, NROWS, DD, FFD);
}